// round 1
// baseline (speedup 1.0000x reference)
#include <cuda_runtime.h>

#define Bsz 2
#define Ssz 2048
#define Dsz 2048
#define Hn 16
#define DHsz 128
#define Msz (Bsz * Ssz)

// Scratch (allocation-free rule: __device__ globals)
__device__ float g_Q[(size_t)Msz * Dsz];   // rope'd q, layout (b*S+s, h*128+dh)
__device__ float g_K[(size_t)Msz * Dsz];   // rope'd k
__device__ float g_V[(size_t)Msz * Dsz];   // v
__device__ float g_lse[Bsz * Hn * Ssz];    // logsumexp per (b,h,s)
__device__ float g_w[Bsz * Hn * Ssz];      // exp(diag - lse)

// ---------------------------------------------------------------------------
// C = A @ W^T   (A: 4096x2048 row-major, W: 2048x2048 row-major, NT gemm)
// mode 0: C = g_Q, rope epilogue
// mode 1: C = g_K, rope epilogue
// mode 2: C = g_V, plain
// mode 3: A = g_V scaled by g_w per (row, head), C = Cext (final output)
// Tiling: 128x128 block, BK=16, 256 threads, 8x8 per-thread register tile.
// ---------------------------------------------------------------------------
__global__ __launch_bounds__(256, 2)
void gemm_nt(const float* __restrict__ Aext, const float* __restrict__ W,
             float* __restrict__ Cext,
             const float* __restrict__ rc, const float* __restrict__ rs,
             int mode)
{
    __shared__ float As[16][132];   // [k][m], padded
    __shared__ float Bs[16][132];   // [k][n], padded

    const int tid = threadIdx.x;
    const int tx = tid & 15;
    const int ty = tid >> 4;
    const int m0 = blockIdx.y * 128;
    const int n0 = blockIdx.x * 128;

    const float* A = (mode == 3) ? g_V : Aext;
    float* C = (mode == 0) ? g_Q : (mode == 1) ? g_K : (mode == 2) ? g_V : Cext;

    float acc[8][8];
#pragma unroll
    for (int i = 0; i < 8; i++)
#pragma unroll
        for (int j = 0; j < 8; j++) acc[i][j] = 0.f;

    for (int k0 = 0; k0 < Dsz; k0 += 16) {
#pragma unroll
        for (int q = 0; q < 2; q++) {
            int e = q * 256 + tid;          // 0..511
            int row = e >> 2;               // 0..127
            int c4 = e & 3;                 // float4 column within BK=16
            float4 av = *(const float4*)(A + (size_t)(m0 + row) * Dsz + k0 + c4 * 4);
            if (mode == 3) {
                int m = m0 + row;
                // head is constant over a 16-wide k-slab (16 | 128)
                float wv = g_w[((m >> 11) * Hn + (k0 >> 7)) * Ssz + (m & (Ssz - 1))];
                av.x *= wv; av.y *= wv; av.z *= wv; av.w *= wv;
            }
            As[c4 * 4 + 0][row] = av.x; As[c4 * 4 + 1][row] = av.y;
            As[c4 * 4 + 2][row] = av.z; As[c4 * 4 + 3][row] = av.w;

            float4 bv = *(const float4*)(W + (size_t)(n0 + row) * Dsz + k0 + c4 * 4);
            Bs[c4 * 4 + 0][row] = bv.x; Bs[c4 * 4 + 1][row] = bv.y;
            Bs[c4 * 4 + 2][row] = bv.z; Bs[c4 * 4 + 3][row] = bv.w;
        }
        __syncthreads();
#pragma unroll
        for (int k = 0; k < 16; k++) {
            float a[8], b[8];
            *(float4*)(a)     = *(const float4*)(&As[k][ty * 8]);
            *(float4*)(a + 4) = *(const float4*)(&As[k][ty * 8 + 4]);
            *(float4*)(b)     = *(const float4*)(&Bs[k][tx * 8]);
            *(float4*)(b + 4) = *(const float4*)(&Bs[k][tx * 8 + 4]);
#pragma unroll
            for (int i = 0; i < 8; i++)
#pragma unroll
                for (int j = 0; j < 8; j++)
                    acc[i][j] = fmaf(a[i], b[j], acc[i][j]);
        }
        __syncthreads();
    }

    const bool rope = (mode == 0 || mode == 1);
#pragma unroll
    for (int i = 0; i < 8; i++) {
        int m = m0 + ty * 8 + i;
        int srow = m & (Ssz - 1);
        int nbase = n0 + tx * 8;
        if (rope) {
#pragma unroll
            for (int jp = 0; jp < 4; jp++) {
                int p = ((nbase + jp * 2) & (DHsz - 1)) >> 1;  // 0..63
                float c  = rc[srow * 64 + p];
                float sn = rs[srow * 64 + p];
                float te = acc[i][jp * 2];
                float to = acc[i][jp * 2 + 1];
                acc[i][jp * 2]     = te * c  - to * sn;
                acc[i][jp * 2 + 1] = te * sn + to * c;
            }
        }
        float4 v0 = make_float4(acc[i][0], acc[i][1], acc[i][2], acc[i][3]);
        float4 v1 = make_float4(acc[i][4], acc[i][5], acc[i][6], acc[i][7]);
        *(float4*)(C + (size_t)m * Dsz + nbase)     = v0;
        *(float4*)(C + (size_t)m * Dsz + nbase + 4) = v1;
    }
}

// ---------------------------------------------------------------------------
// Row-wise logsumexp of (Q_h K_h^T * scale) per (b,h), streamed over key tiles.
// No max-tracking: scores ~ N(0,1) for this problem (|max| ~ 6), fp32 exp safe.
// Block: 128 queries x (all 2048 keys in tiles of 128). 256 threads, 8x8 tile.
// ---------------------------------------------------------------------------
__global__ __launch_bounds__(256)
void lse_kernel()
{
    __shared__ float Qs[32][132];   // [dh][qi]
    __shared__ float Ks[32][132];   // [dh][kj]

    const int tid = threadIdx.x;
    const int tx = tid & 15;
    const int ty = tid >> 4;
    const int b = blockIdx.z, h = blockIdx.y;
    const int q0 = blockIdx.x * 128;
    const float scale = 0.08838834764831845f;   // DH^-0.5

    const float* Qb = g_Q + (size_t)b * Ssz * Dsz + h * DHsz;
    const float* Kb = g_K + (size_t)b * Ssz * Dsz + h * DHsz;

    float rsum[8];
#pragma unroll
    for (int i = 0; i < 8; i++) rsum[i] = 0.f;

    for (int kt = 0; kt < Ssz; kt += 128) {
        float acc[8][8];
#pragma unroll
        for (int i = 0; i < 8; i++)
#pragma unroll
            for (int j = 0; j < 8; j++) acc[i][j] = 0.f;

        for (int dc = 0; dc < DHsz; dc += 32) {
#pragma unroll
            for (int t = 0; t < 4; t++) {
                int e = t * 256 + tid;      // 0..1023
                int row = e >> 3;           // 0..127
                int c4 = e & 7;             // float4 within 32-wide dh chunk
                float4 qv = *(const float4*)(Qb + (size_t)(q0 + row) * Dsz + dc + c4 * 4);
                Qs[c4 * 4 + 0][row] = qv.x; Qs[c4 * 4 + 1][row] = qv.y;
                Qs[c4 * 4 + 2][row] = qv.z; Qs[c4 * 4 + 3][row] = qv.w;
                float4 kv = *(const float4*)(Kb + (size_t)(kt + row) * Dsz + dc + c4 * 4);
                Ks[c4 * 4 + 0][row] = kv.x; Ks[c4 * 4 + 1][row] = kv.y;
                Ks[c4 * 4 + 2][row] = kv.z; Ks[c4 * 4 + 3][row] = kv.w;
            }
            __syncthreads();
#pragma unroll
            for (int kk = 0; kk < 32; kk++) {
                float a[8], bb[8];
                *(float4*)(a)      = *(const float4*)(&Qs[kk][ty * 8]);
                *(float4*)(a + 4)  = *(const float4*)(&Qs[kk][ty * 8 + 4]);
                *(float4*)(bb)     = *(const float4*)(&Ks[kk][tx * 8]);
                *(float4*)(bb + 4) = *(const float4*)(&Ks[kk][tx * 8 + 4]);
#pragma unroll
                for (int i = 0; i < 8; i++)
#pragma unroll
                    for (int j = 0; j < 8; j++)
                        acc[i][j] = fmaf(a[i], bb[j], acc[i][j]);
            }
            __syncthreads();
        }
        // exp + row-reduce across the 16 tx lanes (within 16-lane shfl groups)
#pragma unroll
        for (int i = 0; i < 8; i++) {
            float part = 0.f;
#pragma unroll
            for (int j = 0; j < 8; j++) part += __expf(acc[i][j] * scale);
            part += __shfl_xor_sync(0xffffffffu, part, 1);
            part += __shfl_xor_sync(0xffffffffu, part, 2);
            part += __shfl_xor_sync(0xffffffffu, part, 4);
            part += __shfl_xor_sync(0xffffffffu, part, 8);
            rsum[i] += part;
        }
    }
    if (tx == 0) {
#pragma unroll
        for (int i = 0; i < 8; i++)
            g_lse[((size_t)b * Hn + h) * Ssz + q0 + ty * 8 + i] = logf(rsum[i]);
    }
}

// ---------------------------------------------------------------------------
// w[b,h,s] = exp(scale * q_s . k_s - lse). One warp per (b,h,s); DH=128=32x4.
// ---------------------------------------------------------------------------
__global__ __launch_bounds__(256)
void wdiag_kernel()
{
    int gw = (blockIdx.x * blockDim.x + threadIdx.x) >> 5;
    int lane = threadIdx.x & 31;
    if (gw >= Bsz * Hn * Ssz) return;
    int s  = gw & (Ssz - 1);
    int bh = gw >> 11;              // b*H + h  (S = 2048)
    int h = bh & (Hn - 1);
    int b = bh >> 4;
    const float* q = g_Q + (size_t)(b * Ssz + s) * Dsz + h * DHsz + lane * 4;
    const float* k = g_K + (size_t)(b * Ssz + s) * Dsz + h * DHsz + lane * 4;
    float4 q4 = *(const float4*)q;
    float4 k4 = *(const float4*)k;
    float d = q4.x * k4.x + q4.y * k4.y + q4.z * k4.z + q4.w * k4.w;
#pragma unroll
    for (int m = 16; m > 0; m >>= 1) d += __shfl_xor_sync(0xffffffffu, d, m);
    if (lane == 0)
        g_w[gw] = __expf(d * 0.08838834764831845f - g_lse[gw]);
}

// ---------------------------------------------------------------------------
extern "C" void kernel_launch(void* const* d_in, const int* in_sizes, int n_in,
                              void* d_out, int out_size)
{
    const float* x  = (const float*)d_in[0];
    const float* rc = (const float*)d_in[1];
    const float* rs = (const float*)d_in[2];
    const float* Wq = (const float*)d_in[3];
    const float* Wk = (const float*)d_in[4];
    const float* Wv = (const float*)d_in[5];
    const float* Wo = (const float*)d_in[6];
    float* out = (float*)d_out;

    dim3 grid(Dsz / 128, Msz / 128);     // (16, 32)

    gemm_nt<<<grid, 256>>>(x, Wq, nullptr, rc, rs, 0);   // Q + rope
    gemm_nt<<<grid, 256>>>(x, Wk, nullptr, rc, rs, 1);   // K + rope
    gemm_nt<<<grid, 256>>>(x, Wv, nullptr, rc, rs, 2);   // V

    lse_kernel<<<dim3(Ssz / 128, Hn, Bsz), 256>>>();     // 512 blocks

    wdiag_kernel<<<(Bsz * Hn * Ssz * 32) / 256, 256>>>(); // 8192 blocks

    gemm_nt<<<grid, 256>>>(x, Wo, out, rc, rs, 3);       // (w*V) @ Wo^T
}